// round 2
// baseline (speedup 1.0000x reference)
#include <cuda_runtime.h>
#include <cstdint>

// ---------------------------------------------------------------------------
// TrilineVAE full pipeline
//  occ[2,1,96,96,96] -> 6x conv3d(k=4,s=2,p=1)+relu -> fc -> reparam ->
//  deltas/softmax/cumsum knots + feats -> separable triline table ->
//  per-point MLP decoder -> pred_occ[2,1,96,96,96], mu[2,128], logvar[2,128]
// ---------------------------------------------------------------------------

#define PRED_SIZE 1769472   // 2*96^3
#define HALF_PRED 884736    // 96^3

// ---------------- scratch (__device__ globals; no allocation) --------------
__device__ __align__(16) float g_act0[2 * 32 * 48 * 48 * 48];   // 7,077,888
__device__ __align__(16) float g_act1[2 * 64 * 24 * 24 * 24];   // 1,769,472
__device__ __align__(16) float g_act2[2 * 128 * 12 * 12 * 12];  //   442,368
__device__ __align__(16) float g_act3raw[4 * 2 * 256 * 216];    //   442,368
__device__ __align__(16) float g_act3[2 * 256 * 216];           //   110,592
__device__ __align__(16) float g_act4raw[8 * 2 * 512 * 27];     //   221,184
__device__ __align__(16) float g_xpad5[2 * 512 * 64];           //    65,536
__device__ __align__(16) float g_flat5[2 * 512];
__device__ __align__(16) float g_z[2 * 128];
__device__ __align__(16) float g_knots[6 * 512];
__device__ __align__(16) float g_feats[2 * 3 * 512 * 32];       //    98,304
__device__ __align__(16) float g_g[2 * 3 * 96 * 32];            //    18,432

// ---------------------------------------------------------------------------
// Generic direct conv3d (k=4, s=2, p=1). One thread = one output position,
// register-tiled over OCT output channels. Weights staged in smem, read back
// as broadcast float4 LDS. Optional IC-split across blocks (writes raw
// partials to per-split slices; reduced later — deterministic, no atomics).
// ---------------------------------------------------------------------------
template <int CIN, int COUT, int SIN, int SOUT, int OCT, int ICT, int ICSPLIT, bool FUSE_BIAS>
__global__ void conv_k(const float* __restrict__ in, const float* __restrict__ wt,
                       const float* __restrict__ bias, float* __restrict__ out) {
    constexpr int POS = SOUT * SOUT * SOUT;
    constexpr int ICR = CIN / ICSPLIT;
    __shared__ float ws[OCT * ICT * 64];

    const int sp     = blockIdx.x % ICSPLIT;
    const int posBlk = blockIdx.x / ICSPLIT;
    const int n      = blockIdx.z;
    const int oc0    = blockIdx.y * OCT;
    const int pos    = posBlk * blockDim.x + threadIdx.x;
    const bool active = (pos < POS);

    int od = 0, oh = 0, ow = 0;
    if (active) { od = pos / (SOUT * SOUT); oh = (pos / SOUT) % SOUT; ow = pos % SOUT; }

    float acc[OCT];
#pragma unroll
    for (int o = 0; o < OCT; o++) acc[o] = 0.f;

    const int icBeg = sp * ICR;
    const float* inN = in + (size_t)n * CIN * SIN * SIN * SIN;

    for (int icc = 0; icc < ICR; icc += ICT) {
        __syncthreads();
        for (int e = threadIdx.x; e < OCT * ICT * 64; e += blockDim.x) {
            int o = e / (ICT * 64);
            int rem = e % (ICT * 64);
            int i2 = rem / 64;
            int tt = rem % 64;
            ws[e] = __ldg(&wt[((size_t)(oc0 + o) * CIN + (icBeg + icc + i2)) * 64 + tt]);
        }
        __syncthreads();
        if (active) {
#pragma unroll
            for (int i2 = 0; i2 < ICT; i2++) {
                const float* inC = inN + (size_t)(icBeg + icc + i2) * SIN * SIN * SIN;
#pragma unroll
                for (int kd = 0; kd < 4; kd++) {
                    int id = 2 * od - 1 + kd;
                    if ((unsigned)id >= (unsigned)SIN) continue;
#pragma unroll
                    for (int kh = 0; kh < 4; kh++) {
                        int ih = 2 * oh - 1 + kh;
                        if ((unsigned)ih >= (unsigned)SIN) continue;
                        const float* row = inC + ((size_t)id * SIN + ih) * SIN + (2 * ow - 1);
                        float i0 = (ow > 0) ? __ldg(row + 0) : 0.f;
                        float i1 = __ldg(row + 1);
                        float i2v = __ldg(row + 2);
                        float i3 = (ow < SOUT - 1) ? __ldg(row + 3) : 0.f;
#pragma unroll
                        for (int o = 0; o < OCT; o++) {
                            float4 wv = *reinterpret_cast<const float4*>(
                                &ws[(o * ICT + i2) * 64 + kd * 16 + kh * 4]);
                            float a = acc[o];
                            a = fmaf(i0, wv.x, a);
                            a = fmaf(i1, wv.y, a);
                            a = fmaf(i2v, wv.z, a);
                            a = fmaf(i3, wv.w, a);
                            acc[o] = a;
                        }
                    }
                }
            }
        }
    }

    if (active) {
        size_t obase = ((size_t)n * COUT + oc0) * POS + pos;
        if (FUSE_BIAS) {
#pragma unroll
            for (int o = 0; o < OCT; o++)
                out[obase + (size_t)o * POS] = fmaxf(acc[o] + __ldg(&bias[oc0 + o]), 0.f);
        } else {
            float* outS = out + (size_t)sp * (2ull * COUT * POS);
#pragma unroll
            for (int o = 0; o < OCT; o++)
                outS[obase + (size_t)o * POS] = acc[o];
        }
    }
}

// reduce 4 IC-split slices of conv3, add bias, relu -> act3
__global__ void reduce3_k(const float* __restrict__ b3) {
    int idx = blockIdx.x * 256 + threadIdx.x;
    if (idx >= 2 * 256 * 216) return;
    float s = __ldg(&b3[(idx / 216) % 256]);
#pragma unroll
    for (int q = 0; q < 4; q++) s += g_act3raw[q * 110592 + idx];
    g_act3[idx] = fmaxf(s, 0.f);
}

// reduce 8 IC-split slices of conv4, add bias, relu, scatter into the
// zero-padded im2col vector for conv5 (layout [n][ic][kd][kh][kw], 4^3 taps,
// valid taps have kd,kh,kw >= 1 mapping to act4 spatial 3^3).
__global__ void pad45_k(const float* __restrict__ b4) {
    int idx = blockIdx.x * 256 + threadIdx.x;  // < 65536
    int n = idx >> 15;
    int r = idx & 32767;
    int ic = r >> 6;
    int tt = r & 63;
    int kd = tt >> 4, kh = (tt >> 2) & 3, kw = tt & 3;
    float val = 0.f;
    if (kd >= 1 && kh >= 1 && kw >= 1) {
        int base = (n * 512 + ic) * 27 + (kd - 1) * 9 + (kh - 1) * 3 + (kw - 1);
        float s = __ldg(&b4[ic]);
#pragma unroll
        for (int q = 0; q < 8; q++) s += g_act4raw[q * 27648 + base];
        val = fmaxf(s, 0.f);
    }
    g_xpad5[idx] = val;
}

// conv5 as dot products: out[n,oc] = xpad[n] . W5[oc]  (K = 512*64 = 32768)
__global__ void conv5_k(const float* __restrict__ w5, const float* __restrict__ b5) {
    const int oc = blockIdx.x;
    const int t = threadIdx.x;
    const float* wr = w5 + (size_t)oc * 32768;
    float a0 = 0.f, a1 = 0.f;
    for (int k = t * 4; k < 32768; k += 1024) {
        float4 w = *reinterpret_cast<const float4*>(wr + k);
        float4 x0 = *reinterpret_cast<const float4*>(g_xpad5 + k);
        float4 x1 = *reinterpret_cast<const float4*>(g_xpad5 + 32768 + k);
        a0 = fmaf(w.x, x0.x, a0); a0 = fmaf(w.y, x0.y, a0);
        a0 = fmaf(w.z, x0.z, a0); a0 = fmaf(w.w, x0.w, a0);
        a1 = fmaf(w.x, x1.x, a1); a1 = fmaf(w.y, x1.y, a1);
        a1 = fmaf(w.z, x1.z, a1); a1 = fmaf(w.w, x1.w, a1);
    }
    __shared__ float s0[8], s1[8];
    int lane = t & 31, wid = t >> 5;
#pragma unroll
    for (int off = 16; off; off >>= 1) {
        a0 += __shfl_down_sync(0xffffffffu, a0, off);
        a1 += __shfl_down_sync(0xffffffffu, a1, off);
    }
    if (lane == 0) { s0[wid] = a0; s1[wid] = a1; }
    __syncthreads();
    if (t == 0) {
        float r0 = 0.f, r1 = 0.f;
#pragma unroll
        for (int q = 0; q < 8; q++) { r0 += s0[q]; r1 += s1[q]; }
        float bb = __ldg(&b5[oc]);
        g_flat5[oc]       = fmaxf(r0 + bb, 0.f);
        g_flat5[512 + oc] = fmaxf(r1 + bb, 0.f);
    }
}

// fc -> stats -> mu/logvar -> z ; writes mu, logvar to d_out tail
__global__ void head1_k(const float* __restrict__ fc_w, const float* __restrict__ fc_b,
                        const float* __restrict__ eps, float* __restrict__ d_out) {
    __shared__ float fs[1024];
    __shared__ float stats[512];
    int t = threadIdx.x;  // 256
    for (int e = t; e < 1024; e += 256) fs[e] = g_flat5[e];
    __syncthreads();
    {
        float a0 = __ldg(&fc_b[t]), a1 = a0;
        for (int i = 0; i < 512; i++) {
            float w = __ldg(&fc_w[i * 256 + t]);
            a0 = fmaf(fs[i], w, a0);
            a1 = fmaf(fs[512 + i], w, a1);
        }
        stats[t] = a0;
        stats[256 + t] = a1;
    }
    __syncthreads();
    int n = t >> 7, jj = t & 127;
    float mu = stats[n * 256 + jj];
    float lv = stats[n * 256 + 128 + jj];
    g_z[t] = mu + __ldg(&eps[t]) * expf(0.5f * lv);
    d_out[PRED_SIZE + t] = mu;
    d_out[PRED_SIZE + 256 + t] = lv;
}

// feats = relu(z @ fl_w + fl_b) -> [2,3,512,32] flat
__global__ void feats_k(const float* __restrict__ fl_w, const float* __restrict__ fl_b) {
    __shared__ float zs[128];
    int gid = blockIdx.x * 256 + threadIdx.x;  // < 98304 (blocks never straddle n)
    int n = gid / 49152;
    int o = gid % 49152;
    if (threadIdx.x < 128) zs[threadIdx.x] = g_z[n * 128 + threadIdx.x];
    __syncthreads();
    float a = __ldg(&fl_b[o]);
#pragma unroll 4
    for (int i = 0; i < 128; i++) a = fmaf(zs[i], __ldg(&fl_w[(size_t)i * 49152 + o]), a);
    g_feats[gid] = fmaxf(a, 0.f);
}

// deltas row -> softmax -> cumsum -> knots  (one block per (b,axis))
__global__ void deltas_k(const float* __restrict__ dl_w, const float* __restrict__ dl_b) {
    int b = blockIdx.x / 3, ax = blockIdx.x % 3;
    int t = threadIdx.x;  // 512
    __shared__ float zs[128];
    __shared__ float v[512];
    __shared__ float r[512];
    if (t < 128) zs[t] = g_z[b * 128 + t];
    __syncthreads();
    float val = -1e30f;
    if (t < 511) {
        float a = __ldg(&dl_b[ax * 511 + t]);
        for (int i = 0; i < 128; i++)
            a = fmaf(zs[i], __ldg(&dl_w[i * 1533 + ax * 511 + t]), a);
        val = a;
    }
    // block max
    r[t] = val;
    __syncthreads();
    for (int s = 256; s > 0; s >>= 1) {
        if (t < s) r[t] = fmaxf(r[t], r[t + s]);
        __syncthreads();
    }
    float mx = r[0];
    __syncthreads();
    float e = (t < 511) ? expf(val - mx) : 0.f;
    r[t] = e;
    __syncthreads();
    for (int s = 256; s > 0; s >>= 1) {
        if (t < s) r[t] += r[t + s];
        __syncthreads();
    }
    float sum = r[0];
    __syncthreads();
    v[t] = e / sum;  // v[511] contributes 0
    __syncthreads();
    // Hillis-Steele inclusive scan over 512 entries
    for (int off = 1; off < 512; off <<= 1) {
        float x = v[t];
        float add = (t >= off) ? v[t - off] : 0.f;
        __syncthreads();
        v[t] = x + add;
        __syncthreads();
    }
    float* kr = g_knots + (b * 3 + ax) * 512;
    if (t == 0) kr[0] = 0.f;
    if (t < 511) kr[t + 1] = v[t];
}

// Separable triline table: interpolate each axis' line features at all 96
// grid coordinates. One block (32 threads = 32 feature dims) per (b,axis,i).
__global__ void gtable_k() {
    int blk = blockIdx.x;  // 576
    int i = blk % 96;
    int ax = (blk / 96) % 3;
    int b = blk / 288;
    const float* kr = g_knots + (b * 3 + ax) * 512;
    float u = (i + 0.5f) * (1.0f / 96.0f);
    int lo = 0, hi = 512;
    while (lo < hi) {
        int mid = (lo + hi) >> 1;
        if (__ldg(&kr[mid]) <= u) lo = mid + 1; else hi = mid;
    }
    int idx = lo - 1;
    idx = max(0, min(idx, 510));
    float t0 = __ldg(&kr[idx]), t1 = __ldg(&kr[idx + 1]);
    float w = (u - t0) / (t1 - t0 + 1e-8f);
    w = fminf(fmaxf(w, 0.f), 1.f);
    int d = threadIdx.x;
    const float* fr = g_feats + (((b * 3 + ax) * 512) + idx) * 32;
    g_g[((b * 3 + ax) * 96 + i) * 32 + d] = fr[d] * (1.f - w) + fr[32 + d] * w;
}

// Decoder: f = g0[i]*g1[j]*g2[k]; h = relu(f@W1+b1); logit = h@w2+b2.
// Each thread does the same (i,j,k) for both batches (shared weight LDS).
__global__ __launch_bounds__(256) void decoder_k(
    const float* __restrict__ w1, const float* __restrict__ b1,
    const float* __restrict__ w2, const float* __restrict__ b2,
    float* __restrict__ out) {
    __shared__ float W1t[64 * 32];  // transposed: W1t[k][j]
    __shared__ float b1s[64], w2s[64];
    int t = threadIdx.x;
    for (int e = t; e < 2048; e += 256) {
        int k = e >> 5, j = e & 31;
        W1t[e] = __ldg(&w1[j * 64 + k]);
    }
    if (t < 64) { b1s[t] = __ldg(&b1[t]); w2s[t] = __ldg(&w2[t]); }
    __syncthreads();

    int p = blockIdx.x * 256 + t;  // < 884736 exactly
    int k = p % 96;
    int ij = p / 96;
    int j = ij % 96;
    int i = ij / 96;

    const float4* a0 = reinterpret_cast<const float4*>(g_g + (0 * 96 + i) * 32);
    const float4* a1 = reinterpret_cast<const float4*>(g_g + (1 * 96 + j) * 32);
    const float4* a2 = reinterpret_cast<const float4*>(g_g + (2 * 96 + k) * 32);
    const float4* c0 = reinterpret_cast<const float4*>(g_g + 9216 + (0 * 96 + i) * 32);
    const float4* c1 = reinterpret_cast<const float4*>(g_g + 9216 + (1 * 96 + j) * 32);
    const float4* c2 = reinterpret_cast<const float4*>(g_g + 9216 + (2 * 96 + k) * 32);

    float fa[32], fb[32];
#pragma unroll
    for (int q = 0; q < 8; q++) {
        float4 x0 = __ldg(a0 + q), x1 = __ldg(a1 + q), x2 = __ldg(a2 + q);
        fa[4 * q + 0] = x0.x * x1.x * x2.x;
        fa[4 * q + 1] = x0.y * x1.y * x2.y;
        fa[4 * q + 2] = x0.z * x1.z * x2.z;
        fa[4 * q + 3] = x0.w * x1.w * x2.w;
        float4 y0 = __ldg(c0 + q), y1 = __ldg(c1 + q), y2 = __ldg(c2 + q);
        fb[4 * q + 0] = y0.x * y1.x * y2.x;
        fb[4 * q + 1] = y0.y * y1.y * y2.y;
        fb[4 * q + 2] = y0.z * y1.z * y2.z;
        fb[4 * q + 3] = y0.w * y1.w * y2.w;
    }

    float bv = __ldg(b2);
    float la = bv, lb = bv;
#pragma unroll 2
    for (int kk = 0; kk < 64; kk++) {
        float aA = b1s[kk], aB = aA;
        const float4* wr = reinterpret_cast<const float4*>(&W1t[kk * 32]);
#pragma unroll
        for (int q = 0; q < 8; q++) {
            float4 w = wr[q];
            aA = fmaf(fa[4 * q + 0], w.x, aA);
            aA = fmaf(fa[4 * q + 1], w.y, aA);
            aA = fmaf(fa[4 * q + 2], w.z, aA);
            aA = fmaf(fa[4 * q + 3], w.w, aA);
            aB = fmaf(fb[4 * q + 0], w.x, aB);
            aB = fmaf(fb[4 * q + 1], w.y, aB);
            aB = fmaf(fb[4 * q + 2], w.z, aB);
            aB = fmaf(fb[4 * q + 3], w.w, aB);
        }
        la = fmaf(fmaxf(aA, 0.f), w2s[kk], la);
        lb = fmaf(fmaxf(aB, 0.f), w2s[kk], lb);
    }
    out[p] = la;
    out[HALF_PRED + p] = lb;
}

// ---------------------------------------------------------------------------
extern "C" void kernel_launch(void* const* d_in, const int* in_sizes, int n_in,
                              void* d_out, int out_size) {
    const float* occ  = (const float*)d_in[0];
    const float* eps  = (const float*)d_in[1];
    const float* cw0  = (const float*)d_in[3];
    const float* cb0  = (const float*)d_in[4];
    const float* cw1  = (const float*)d_in[5];
    const float* cb1  = (const float*)d_in[6];
    const float* cw2  = (const float*)d_in[7];
    const float* cb2  = (const float*)d_in[8];
    const float* cw3  = (const float*)d_in[9];
    const float* cb3  = (const float*)d_in[10];
    const float* cw4  = (const float*)d_in[11];
    const float* cb4  = (const float*)d_in[12];
    const float* cw5  = (const float*)d_in[13];
    const float* cb5  = (const float*)d_in[14];
    const float* fc_w = (const float*)d_in[15];
    const float* fc_b = (const float*)d_in[16];
    const float* dl_w = (const float*)d_in[17];
    const float* dl_b = (const float*)d_in[18];
    const float* fl_w = (const float*)d_in[19];
    const float* fl_b = (const float*)d_in[20];
    const float* w1   = (const float*)d_in[21];
    const float* b1   = (const float*)d_in[22];
    const float* w2   = (const float*)d_in[23];
    const float* b2   = (const float*)d_in[24];
    float* out = (float*)d_out;

    float *a0p, *a1p, *a2p, *a3rp, *a3p, *a4rp;
    cudaGetSymbolAddress((void**)&a0p, g_act0);
    cudaGetSymbolAddress((void**)&a1p, g_act1);
    cudaGetSymbolAddress((void**)&a2p, g_act2);
    cudaGetSymbolAddress((void**)&a3rp, g_act3raw);
    cudaGetSymbolAddress((void**)&a3p, g_act3);
    cudaGetSymbolAddress((void**)&a4rp, g_act4raw);

    // conv0: 1->32, 96->48
    conv_k<1, 32, 96, 48, 8, 1, 1, true><<<dim3(864, 4, 2), 128>>>(occ, cw0, cb0, a0p);
    // conv1: 32->64, 48->24
    conv_k<32, 64, 48, 24, 8, 8, 1, true><<<dim3(108, 8, 2), 128>>>(a0p, cw1, cb1, a1p);
    // conv2: 64->128, 24->12
    conv_k<64, 128, 24, 12, 8, 8, 1, true><<<dim3(14, 16, 2), 128>>>(a1p, cw2, cb2, a2p);
    // conv3: 128->256, 12->6, IC-split 4
    conv_k<128, 256, 12, 6, 8, 8, 4, false><<<dim3(4, 32, 2), 224>>>(a2p, cw3, cb3, a3rp);
    reduce3_k<<<432, 256>>>(cb3);
    // conv4: 256->512, 6->3, IC-split 8
    conv_k<256, 512, 6, 3, 8, 8, 8, false><<<dim3(8, 64, 2), 32>>>(a3p, cw4, cb4, a4rp);
    pad45_k<<<256, 256>>>(cb4);
    // conv5: 512->512, 3->1 (as padded dot-product GEMM)
    conv5_k<<<512, 256>>>(cw5, cb5);
    // fc / reparam / mu,logvar out
    head1_k<<<1, 256>>>(fc_w, fc_b, eps, out);
    // feature lines + knots
    feats_k<<<384, 256>>>(fl_w, fl_b);
    deltas_k<<<6, 512>>>(dl_w, dl_b);
    // separable triline table
    gtable_k<<<576, 32>>>();
    // decoder
    decoder_k<<<3456, 256>>>(w1, b1, w2, b2, out);
}

// round 3
// speedup vs baseline: 1.2117x; 1.2117x over previous
#include <cuda_runtime.h>
#include <cstdint>

// ---------------------------------------------------------------------------
// TrilineVAE full pipeline (smem-tiled direct convs v2)
// ---------------------------------------------------------------------------

#define PRED_SIZE 1769472   // 2*96^3
#define HALF_PRED 884736    // 96^3

// ---------------- scratch (__device__ globals; no allocation) --------------
__device__ __align__(16) float g_act0[2 * 32 * 48 * 48 * 48];   // 7,077,888
__device__ __align__(16) float g_act1[2 * 64 * 24 * 24 * 24];   // 1,769,472
__device__ __align__(16) float g_act2raw[4 * 2 * 128 * 1728];   // 1,769,472
__device__ __align__(16) float g_act2[2 * 128 * 1728];          //   442,368
__device__ __align__(16) float g_act3raw[8 * 2 * 256 * 216];    //   884,736
__device__ __align__(16) float g_act3[2 * 256 * 216];           //   110,592
__device__ __align__(16) float g_act4raw[16 * 2 * 512 * 27];    //   442,368
__device__ __align__(16) float g_xpad5[2 * 512 * 64];           //    65,536
__device__ __align__(16) float g_flat5[2 * 512];
__device__ __align__(16) float g_z[2 * 128];
__device__ __align__(16) float g_knots[6 * 512];
__device__ __align__(16) float g_feats[2 * 3 * 512 * 32];       //    98,304
__device__ __align__(16) float g_g[2 * 3 * 96 * 32];            //    18,432

// ---------------------------------------------------------------------------
// Tiled direct conv3d (k=4, s=2, p=1). Input tile (with halo) AND weight chunk
// staged in smem. Thread computes PT positions x OCT output channels.
// Optional IC-split across blocks (raw partial slices, reduced later).
// ---------------------------------------------------------------------------
template <int CIN, int COUT, int SIN, int SOUT, int TD, int TH, int TW,
          int OCB, int ICT, int ICSPLIT, int PT, int OCT, bool FUSE>
__global__ void convt_k(const float* __restrict__ in, const float* __restrict__ wt,
                        const float* __restrict__ bias, float* __restrict__ out) {
    constexpr int POS_TILE = TD * TH * TW;
    constexpr int NPOS_T = POS_TILE / PT;
    constexpr int NOC_T = OCB / OCT;
    constexpr int BLK = NPOS_T * NOC_T;
    constexpr int TD2 = 2 * TD + 2, TH2 = 2 * TH + 2, TW2 = 2 * TW + 2;
    constexpr int INEL = TD2 * TH2 * TW2;
    constexpr int POS_OUT = SOUT * SOUT * SOUT;
    constexpr int ICR = CIN / ICSPLIT;
    constexpr int NT_W = SOUT / TW, NT_H = SOUT / TH;

    __shared__ __align__(16) float sIn[ICT * INEL];
    __shared__ __align__(16) float sW[OCB * ICT * 64];

    const int tid = threadIdx.x;
    const int n = blockIdx.z;
    const int oc0 = blockIdx.y * OCB;
    int bx = blockIdx.x;
    const int sp = bx % ICSPLIT; bx /= ICSPLIT;
    const int twi = bx % NT_W; bx /= NT_W;
    const int thi = bx % NT_H; bx /= NT_H;
    const int tdi = bx;
    const int od0 = tdi * TD, oh0 = thi * TH, ow0 = twi * TW;
    const int id0 = 2 * od0 - 1, ih0 = 2 * oh0 - 1, iw0 = 2 * ow0 - 1;
    const int icBeg = sp * ICR;

    const int posT = tid % NPOS_T;
    const int ocT = tid / NPOS_T;

    int baseq[PT];
    int gpos[PT];
#pragma unroll
    for (int q = 0; q < PT; q++) {
        int p = posT + q * NPOS_T;
        int owl = p % TW;
        int ohl = (p / TW) % TH;
        int odl = p / (TW * TH);
        baseq[q] = (2 * odl) * TH2 * TW2 + (2 * ohl) * TW2 + 2 * owl;
        gpos[q] = ((od0 + odl) * SOUT + (oh0 + ohl)) * SOUT + (ow0 + owl);
    }

    float acc[PT * OCT];
#pragma unroll
    for (int i = 0; i < PT * OCT; i++) acc[i] = 0.f;

    const float* inN = in + (size_t)n * CIN * SIN * SIN * SIN;

    for (int icc = 0; icc < ICR; icc += ICT) {
        __syncthreads();
        // stage input tile (with halo, zero-padded)
        for (int e = tid; e < ICT * INEL; e += BLK) {
            int icl = e / INEL;
            int r = e % INEL;
            int dd = r / (TH2 * TW2);
            int hh = (r / TW2) % TH2;
            int ww = r % TW2;
            int id = id0 + dd, ih = ih0 + hh, iw = iw0 + ww;
            float v = 0.f;
            if ((unsigned)id < (unsigned)SIN && (unsigned)ih < (unsigned)SIN &&
                (unsigned)iw < (unsigned)SIN)
                v = __ldg(&inN[(((size_t)(icBeg + icc + icl) * SIN + id) * SIN + ih) * SIN + iw]);
            sIn[e] = v;
        }
        // stage weight chunk
        for (int e = tid; e < OCB * ICT * 64; e += BLK) {
            int o = e / (ICT * 64);
            int r = e % (ICT * 64);
            int icl = r / 64;
            int t = r % 64;
            sW[e] = __ldg(&wt[((size_t)(oc0 + o) * CIN + (icBeg + icc + icl)) * 64 + t]);
        }
        __syncthreads();

#pragma unroll
        for (int icl = 0; icl < ICT; icl++) {
            const float* inL = sIn + icl * INEL;
#pragma unroll
            for (int kd = 0; kd < 4; kd++) {
#pragma unroll
                for (int kh = 0; kh < 4; kh++) {
                    const float* row = inL + kd * TH2 * TW2 + kh * TW2;
                    float xv[PT][4];
#pragma unroll
                    for (int q = 0; q < PT; q++) {
                        const float* rp = row + baseq[q];
                        xv[q][0] = rp[0];
                        xv[q][1] = rp[1];
                        xv[q][2] = rp[2];
                        xv[q][3] = rp[3];
                    }
#pragma unroll
                    for (int j = 0; j < OCT; j++) {
                        float4 wv = *reinterpret_cast<const float4*>(
                            sW + ((ocT * OCT + j) * ICT + icl) * 64 + kd * 16 + kh * 4);
#pragma unroll
                        for (int q = 0; q < PT; q++) {
                            float a = acc[q * OCT + j];
                            a = fmaf(xv[q][0], wv.x, a);
                            a = fmaf(xv[q][1], wv.y, a);
                            a = fmaf(xv[q][2], wv.z, a);
                            a = fmaf(xv[q][3], wv.w, a);
                            acc[q * OCT + j] = a;
                        }
                    }
                }
            }
        }
    }

    if (FUSE) {
#pragma unroll
        for (int j = 0; j < OCT; j++) {
            int oc = oc0 + ocT * OCT + j;
            float bb = __ldg(&bias[oc]);
#pragma unroll
            for (int q = 0; q < PT; q++)
                out[((size_t)n * COUT + oc) * POS_OUT + gpos[q]] =
                    fmaxf(acc[q * OCT + j] + bb, 0.f);
        }
    } else {
        float* outS = out + (size_t)sp * (2ull * COUT * POS_OUT);
#pragma unroll
        for (int j = 0; j < OCT; j++) {
            int oc = oc0 + ocT * OCT + j;
#pragma unroll
            for (int q = 0; q < PT; q++)
                outS[((size_t)n * COUT + oc) * POS_OUT + gpos[q]] = acc[q * OCT + j];
        }
    }
}

// generic slice reducer: sum NS slices + bias + relu
template <int NS, int TOTAL, int PP, int COUT>
__global__ void reduceN_k(const float* __restrict__ raw, const float* __restrict__ bias,
                          float* __restrict__ out) {
    int idx = blockIdx.x * 256 + threadIdx.x;
    if (idx >= TOTAL) return;
    float s = __ldg(&bias[(idx / PP) % COUT]);
#pragma unroll
    for (int q = 0; q < NS; q++) s += raw[(size_t)q * TOTAL + idx];
    out[idx] = fmaxf(s, 0.f);
}

// reduce 16 IC-split slices of conv4, add bias, relu, scatter into the
// zero-padded im2col vector for conv5 (layout [n][ic][kd][kh][kw]).
__global__ void pad45_k(const float* __restrict__ b4) {
    int idx = blockIdx.x * 256 + threadIdx.x;  // < 65536
    int n = idx >> 15;
    int r = idx & 32767;
    int ic = r >> 6;
    int tt = r & 63;
    int kd = tt >> 4, kh = (tt >> 2) & 3, kw = tt & 3;
    float val = 0.f;
    if (kd >= 1 && kh >= 1 && kw >= 1) {
        int base = (n * 512 + ic) * 27 + (kd - 1) * 9 + (kh - 1) * 3 + (kw - 1);
        float s = __ldg(&b4[ic]);
#pragma unroll
        for (int q = 0; q < 16; q++) s += g_act4raw[q * 27648 + base];
        val = fmaxf(s, 0.f);
    }
    g_xpad5[idx] = val;
}

// conv5 as dot products: out[n,oc] = xpad[n] . W5[oc]  (K = 512*64 = 32768)
__global__ void conv5_k(const float* __restrict__ w5, const float* __restrict__ b5) {
    const int oc = blockIdx.x;
    const int t = threadIdx.x;
    const float* wr = w5 + (size_t)oc * 32768;
    float a0 = 0.f, a1 = 0.f;
    for (int k = t * 4; k < 32768; k += 1024) {
        float4 w = *reinterpret_cast<const float4*>(wr + k);
        float4 x0 = *reinterpret_cast<const float4*>(g_xpad5 + k);
        float4 x1 = *reinterpret_cast<const float4*>(g_xpad5 + 32768 + k);
        a0 = fmaf(w.x, x0.x, a0); a0 = fmaf(w.y, x0.y, a0);
        a0 = fmaf(w.z, x0.z, a0); a0 = fmaf(w.w, x0.w, a0);
        a1 = fmaf(w.x, x1.x, a1); a1 = fmaf(w.y, x1.y, a1);
        a1 = fmaf(w.z, x1.z, a1); a1 = fmaf(w.w, x1.w, a1);
    }
    __shared__ float s0[8], s1[8];
    int lane = t & 31, wid = t >> 5;
#pragma unroll
    for (int off = 16; off; off >>= 1) {
        a0 += __shfl_down_sync(0xffffffffu, a0, off);
        a1 += __shfl_down_sync(0xffffffffu, a1, off);
    }
    if (lane == 0) { s0[wid] = a0; s1[wid] = a1; }
    __syncthreads();
    if (t == 0) {
        float r0 = 0.f, r1 = 0.f;
#pragma unroll
        for (int q = 0; q < 8; q++) { r0 += s0[q]; r1 += s1[q]; }
        float bb = __ldg(&b5[oc]);
        g_flat5[oc]       = fmaxf(r0 + bb, 0.f);
        g_flat5[512 + oc] = fmaxf(r1 + bb, 0.f);
    }
}

// fc -> stats -> mu/logvar -> z ; writes mu, logvar to d_out tail
__global__ void head1_k(const float* __restrict__ fc_w, const float* __restrict__ fc_b,
                        const float* __restrict__ eps, float* __restrict__ d_out) {
    __shared__ float fs[1024];
    __shared__ float stats[512];
    int t = threadIdx.x;  // 256
    for (int e = t; e < 1024; e += 256) fs[e] = g_flat5[e];
    __syncthreads();
    {
        float a0 = __ldg(&fc_b[t]), a1 = a0;
        for (int i = 0; i < 512; i++) {
            float w = __ldg(&fc_w[i * 256 + t]);
            a0 = fmaf(fs[i], w, a0);
            a1 = fmaf(fs[512 + i], w, a1);
        }
        stats[t] = a0;
        stats[256 + t] = a1;
    }
    __syncthreads();
    int n = t >> 7, jj = t & 127;
    float mu = stats[n * 256 + jj];
    float lv = stats[n * 256 + 128 + jj];
    g_z[t] = mu + __ldg(&eps[t]) * expf(0.5f * lv);
    d_out[PRED_SIZE + t] = mu;
    d_out[PRED_SIZE + 256 + t] = lv;
}

// feats = relu(z @ fl_w + fl_b) -> [2,3,512,32]; both batches per thread
__global__ void feats_k(const float* __restrict__ fl_w, const float* __restrict__ fl_b) {
    __shared__ float zs[256];
    int t = threadIdx.x;
    int gid = blockIdx.x * 256 + t;  // < 49152
    zs[t] = g_z[t];
    __syncthreads();
    float b = __ldg(&fl_b[gid]);
    float a0 = b, a1 = b;
#pragma unroll 4
    for (int i = 0; i < 128; i++) {
        float w = __ldg(&fl_w[(size_t)i * 49152 + gid]);
        a0 = fmaf(zs[i], w, a0);
        a1 = fmaf(zs[128 + i], w, a1);
    }
    g_feats[gid] = fmaxf(a0, 0.f);
    g_feats[49152 + gid] = fmaxf(a1, 0.f);
}

// deltas row -> softmax -> cumsum -> knots  (one block per (b,axis))
__global__ void deltas_k(const float* __restrict__ dl_w, const float* __restrict__ dl_b) {
    int b = blockIdx.x / 3, ax = blockIdx.x % 3;
    int t = threadIdx.x;  // 512
    __shared__ float zs[128];
    __shared__ float v[512];
    __shared__ float r[512];
    if (t < 128) zs[t] = g_z[b * 128 + t];
    __syncthreads();
    float val = -1e30f;
    if (t < 511) {
        float a = __ldg(&dl_b[ax * 511 + t]);
        for (int i = 0; i < 128; i++)
            a = fmaf(zs[i], __ldg(&dl_w[i * 1533 + ax * 511 + t]), a);
        val = a;
    }
    r[t] = val;
    __syncthreads();
    for (int s = 256; s > 0; s >>= 1) {
        if (t < s) r[t] = fmaxf(r[t], r[t + s]);
        __syncthreads();
    }
    float mx = r[0];
    __syncthreads();
    float e = (t < 511) ? expf(val - mx) : 0.f;
    r[t] = e;
    __syncthreads();
    for (int s = 256; s > 0; s >>= 1) {
        if (t < s) r[t] += r[t + s];
        __syncthreads();
    }
    float sum = r[0];
    __syncthreads();
    v[t] = e / sum;
    __syncthreads();
    for (int off = 1; off < 512; off <<= 1) {
        float x = v[t];
        float add = (t >= off) ? v[t - off] : 0.f;
        __syncthreads();
        v[t] = x + add;
        __syncthreads();
    }
    float* kr = g_knots + (b * 3 + ax) * 512;
    if (t == 0) kr[0] = 0.f;
    if (t < 511) kr[t + 1] = v[t];
}

// Separable triline table: one block (32 threads) per (b,axis,i).
__global__ void gtable_k() {
    int blk = blockIdx.x;  // 576
    int i = blk % 96;
    int ax = (blk / 96) % 3;
    int b = blk / 288;
    const float* kr = g_knots + (b * 3 + ax) * 512;
    float u = (i + 0.5f) * (1.0f / 96.0f);
    int lo = 0, hi = 512;
    while (lo < hi) {
        int mid = (lo + hi) >> 1;
        if (__ldg(&kr[mid]) <= u) lo = mid + 1; else hi = mid;
    }
    int idx = lo - 1;
    idx = max(0, min(idx, 510));
    float t0 = __ldg(&kr[idx]), t1 = __ldg(&kr[idx + 1]);
    float w = (u - t0) / (t1 - t0 + 1e-8f);
    w = fminf(fmaxf(w, 0.f), 1.f);
    int d = threadIdx.x;
    const float* fr = g_feats + (((b * 3 + ax) * 512) + idx) * 32;
    g_g[((b * 3 + ax) * 96 + i) * 32 + d] = fr[d] * (1.f - w) + fr[32 + d] * w;
}

// Decoder: f = g0[i]*g1[j]*g2[k]; h = relu(f@W1+b1); logit = h@w2+b2.
__global__ __launch_bounds__(256) void decoder_k(
    const float* __restrict__ w1, const float* __restrict__ b1,
    const float* __restrict__ w2, const float* __restrict__ b2,
    float* __restrict__ out) {
    __shared__ float W1t[64 * 32];
    __shared__ float b1s[64], w2s[64];
    int t = threadIdx.x;
    for (int e = t; e < 2048; e += 256) {
        int k = e >> 5, j = e & 31;
        W1t[e] = __ldg(&w1[j * 64 + k]);
    }
    if (t < 64) { b1s[t] = __ldg(&b1[t]); w2s[t] = __ldg(&w2[t]); }
    __syncthreads();

    int p = blockIdx.x * 256 + t;
    int k = p % 96;
    int ij = p / 96;
    int j = ij % 96;
    int i = ij / 96;

    const float4* a0 = reinterpret_cast<const float4*>(g_g + (0 * 96 + i) * 32);
    const float4* a1 = reinterpret_cast<const float4*>(g_g + (1 * 96 + j) * 32);
    const float4* a2 = reinterpret_cast<const float4*>(g_g + (2 * 96 + k) * 32);
    const float4* c0 = reinterpret_cast<const float4*>(g_g + 9216 + (0 * 96 + i) * 32);
    const float4* c1 = reinterpret_cast<const float4*>(g_g + 9216 + (1 * 96 + j) * 32);
    const float4* c2 = reinterpret_cast<const float4*>(g_g + 9216 + (2 * 96 + k) * 32);

    float fa[32], fb[32];
#pragma unroll
    for (int q = 0; q < 8; q++) {
        float4 x0 = __ldg(a0 + q), x1 = __ldg(a1 + q), x2 = __ldg(a2 + q);
        fa[4 * q + 0] = x0.x * x1.x * x2.x;
        fa[4 * q + 1] = x0.y * x1.y * x2.y;
        fa[4 * q + 2] = x0.z * x1.z * x2.z;
        fa[4 * q + 3] = x0.w * x1.w * x2.w;
        float4 y0 = __ldg(c0 + q), y1 = __ldg(c1 + q), y2 = __ldg(c2 + q);
        fb[4 * q + 0] = y0.x * y1.x * y2.x;
        fb[4 * q + 1] = y0.y * y1.y * y2.y;
        fb[4 * q + 2] = y0.z * y1.z * y2.z;
        fb[4 * q + 3] = y0.w * y1.w * y2.w;
    }

    float bv = __ldg(b2);
    float la = bv, lb = bv;
#pragma unroll 2
    for (int kk = 0; kk < 64; kk++) {
        float aA = b1s[kk], aB = aA;
        const float4* wr = reinterpret_cast<const float4*>(&W1t[kk * 32]);
#pragma unroll
        for (int q = 0; q < 8; q++) {
            float4 w = wr[q];
            aA = fmaf(fa[4 * q + 0], w.x, aA);
            aA = fmaf(fa[4 * q + 1], w.y, aA);
            aA = fmaf(fa[4 * q + 2], w.z, aA);
            aA = fmaf(fa[4 * q + 3], w.w, aA);
            aB = fmaf(fb[4 * q + 0], w.x, aB);
            aB = fmaf(fb[4 * q + 1], w.y, aB);
            aB = fmaf(fb[4 * q + 2], w.z, aB);
            aB = fmaf(fb[4 * q + 3], w.w, aB);
        }
        la = fmaf(fmaxf(aA, 0.f), w2s[kk], la);
        lb = fmaf(fmaxf(aB, 0.f), w2s[kk], lb);
    }
    out[p] = la;
    out[HALF_PRED + p] = lb;
}

// ---------------------------------------------------------------------------
extern "C" void kernel_launch(void* const* d_in, const int* in_sizes, int n_in,
                              void* d_out, int out_size) {
    const float* occ  = (const float*)d_in[0];
    const float* eps  = (const float*)d_in[1];
    const float* cw0  = (const float*)d_in[3];
    const float* cb0  = (const float*)d_in[4];
    const float* cw1  = (const float*)d_in[5];
    const float* cb1  = (const float*)d_in[6];
    const float* cw2  = (const float*)d_in[7];
    const float* cb2  = (const float*)d_in[8];
    const float* cw3  = (const float*)d_in[9];
    const float* cb3  = (const float*)d_in[10];
    const float* cw4  = (const float*)d_in[11];
    const float* cb4  = (const float*)d_in[12];
    const float* cw5  = (const float*)d_in[13];
    const float* cb5  = (const float*)d_in[14];
    const float* fc_w = (const float*)d_in[15];
    const float* fc_b = (const float*)d_in[16];
    const float* dl_w = (const float*)d_in[17];
    const float* dl_b = (const float*)d_in[18];
    const float* fl_w = (const float*)d_in[19];
    const float* fl_b = (const float*)d_in[20];
    const float* w1   = (const float*)d_in[21];
    const float* b1   = (const float*)d_in[22];
    const float* w2   = (const float*)d_in[23];
    const float* b2   = (const float*)d_in[24];
    float* out = (float*)d_out;

    float *a0p, *a1p, *a2rp, *a2p, *a3rp, *a3p, *a4rp;
    cudaGetSymbolAddress((void**)&a0p, g_act0);
    cudaGetSymbolAddress((void**)&a1p, g_act1);
    cudaGetSymbolAddress((void**)&a2rp, g_act2raw);
    cudaGetSymbolAddress((void**)&a2p, g_act2);
    cudaGetSymbolAddress((void**)&a3rp, g_act3raw);
    cudaGetSymbolAddress((void**)&a3p, g_act3);
    cudaGetSymbolAddress((void**)&a4rp, g_act4raw);

    // conv0: 1->32, 96->48, tile 8x8x8, OCB16, fused
    convt_k<1, 32, 96, 48, 8, 8, 8, 16, 1, 1, 4, 8, true>
        <<<dim3(216, 2, 2), 256>>>(occ, cw0, cb0, a0p);
    // conv1: 32->64, 48->24, tile 4x8x8, OCB16, ICT2, fused
    convt_k<32, 64, 48, 24, 4, 8, 8, 16, 2, 1, 4, 8, true>
        <<<dim3(54, 4, 2), 128>>>(a0p, cw1, cb1, a1p);
    // conv2: 64->128, 24->12, tile 6x6x12, OCB16, ICSPLIT4
    convt_k<64, 128, 24, 12, 6, 6, 12, 16, 1, 4, 4, 8, false>
        <<<dim3(16, 8, 2), 216>>>(a1p, cw2, cb2, a2rp);
    reduceN_k<4, 442368, 1728, 128><<<1728, 256>>>(a2rp, cb2, a2p);
    // conv3: 128->256, 12->6, tile 6x6x6, OCB32, ICT2, ICSPLIT8
    convt_k<128, 256, 12, 6, 6, 6, 6, 32, 2, 8, 4, 8, false>
        <<<dim3(8, 8, 2), 216>>>(a2p, cw3, cb3, a3rp);
    reduceN_k<8, 110592, 216, 256><<<432, 256>>>(a3rp, cb3, a3p);
    // conv4: 256->512, 6->3, tile 3x3x3, OCB32, ICT4, ICSPLIT16
    convt_k<256, 512, 6, 3, 3, 3, 3, 32, 4, 16, 1, 8, false>
        <<<dim3(16, 16, 2), 108>>>(a3p, cw4, cb4, a4rp);
    pad45_k<<<256, 256>>>(cb4);
    // conv5: 512->512, 3->1 (padded dot-product)
    conv5_k<<<512, 256>>>(cw5, cb5);
    // fc / reparam / mu,logvar out
    head1_k<<<1, 256>>>(fc_w, fc_b, eps, out);
    // feature lines + knots
    feats_k<<<192, 256>>>(fl_w, fl_b);
    deltas_k<<<6, 512>>>(dl_w, dl_b);
    // separable triline table
    gtable_k<<<576, 32>>>();
    // decoder
    decoder_k<<<3456, 256>>>(w1, b1, w2, b2, out);
}